// round 13
// baseline (speedup 1.0000x reference)
#include <cuda_runtime.h>
#include <cuda_bf16.h>
#include <math.h>

// Problem constants
#define ROWS_TOTAL 32768
#define K_DIM 1024
#define ANCHORS 8
#define PRED_ELEMS (ROWS_TOTAL * ANCHORS)   // 262144

// One 512-thread CTA = 16 autonomous warps. Warp w owns rows row0+4w..+3,
// all 16 outputs. Block covers 64 rows.
#define THREADS 512
#define WARPS_PER_BLOCK 16
#define ROWS_PER_WARP 4
#define ROWS_PER_BLOCK 64
#define NBLOCKS (ROWS_TOTAL / ROWS_PER_BLOCK)   // 512
#define NCHUNKS 32                              // K chunks of 32
#define D_PRE 8                                 // X register-prefetch depth (chunks)

// W in shared, padded stride 20 floats. LDS.128 8-lane phase banks
// 20L mod 32 = {0,20,8,28,16,4,24,12} -> all 32 banks once -> conflict-free.
#define W_STRIDE 20
#define W_FLOATS (K_DIM * W_STRIDE)             // 80KB
#define SMEM_BYTES (W_FLOATS * 4)               // 81920

__device__ float g_part_nll[NBLOCKS];
__device__ int   g_part_cnt[NBLOCKS];
__device__ unsigned int g_done;   // zero-init; finalizer resets -> replay-safe

__device__ __forceinline__ void fma2(unsigned long long& d,
                                     unsigned long long a,
                                     unsigned long long b) {
    asm("fma.rn.f32x2 %0, %1, %2, %0;" : "+l"(d) : "l"(a), "l"(b));
}
__device__ __forceinline__ unsigned long long add2r(unsigned long long a,
                                                    unsigned long long b) {
    asm("add.rn.f32x2 %0, %0, %1;" : "+l"(a) : "l"(b));
    return a;
}
__device__ __forceinline__ unsigned long long pack_dup(float x) {
    unsigned long long r;
    asm("mov.b64 %0, {%1, %1};" : "=l"(r) : "r"(__float_as_uint(x)));
    return r;
}
__device__ __forceinline__ void unpack2(unsigned long long v, float& lo, float& hi) {
    unsigned int l, h;
    asm("mov.b64 {%0, %1}, %2;" : "=r"(l), "=r"(h) : "l"(v));
    lo = __uint_as_float(l);
    hi = __uint_as_float(h);
}

// One chunk of work: 4 conflict-free W LDS.128 + 32 FFMA2 on packed accumulators.
__device__ __forceinline__ void do_chunk(unsigned long long* __restrict__ acc,
                                         const float* __restrict__ Wsh,
                                         const float* __restrict__ xs,   // [4]
                                         int c, int lane) {
    const float* wp = Wsh + (c * 32 + lane) * W_STRIDE;
    const ulonglong2 wa = *reinterpret_cast<const ulonglong2*>(wp);
    const ulonglong2 wb = *reinterpret_cast<const ulonglong2*>(wp + 4);
    const ulonglong2 wc = *reinterpret_cast<const ulonglong2*>(wp + 8);
    const ulonglong2 wd = *reinterpret_cast<const ulonglong2*>(wp + 12);
#pragma unroll
    for (int r = 0; r < ROWS_PER_WARP; ++r) {
        const unsigned long long xx = pack_dup(xs[r]);
        fma2(acc[r * 8 + 0], xx, wa.x);
        fma2(acc[r * 8 + 1], xx, wa.y);
        fma2(acc[r * 8 + 2], xx, wb.x);
        fma2(acc[r * 8 + 3], xx, wb.y);
        fma2(acc[r * 8 + 4], xx, wc.x);
        fma2(acc[r * 8 + 5], xx, wc.y);
        fma2(acc[r * 8 + 6], xx, wd.x);
        fma2(acc[r * 8 + 7], xx, wd.y);
    }
}

__global__ __launch_bounds__(THREADS, 1)
void rpn_main_kernel(const float*  __restrict__ Xf,     // [32768][1024]
                     const float*  __restrict__ Wg,     // [1024][16]
                     const float*  __restrict__ bias,   // [16]
                     const int*    __restrict__ labels, // [32768][8]
                     float* __restrict__ out)
{
    extern __shared__ __align__(16) float Wsh[];   // [1024][20]
    __shared__ float s_nll[WARPS_PER_BLOCK];
    __shared__ int   s_cnt[WARPS_PER_BLOCK];
    __shared__ int   s_last;

    const int tid  = threadIdx.x;
    const int wid  = tid >> 5;
    const int lane = tid & 31;
    const int wrow0 = blockIdx.x * ROWS_PER_BLOCK + wid * ROWS_PER_WARP;

    // Stage W (vectorized STS.128 into padded layout)
    {
        const float4* Wg4 = reinterpret_cast<const float4*>(Wg);
        for (int i = tid; i < K_DIM * 4; i += THREADS) {
            const int k  = i >> 2;
            const int n0 = (i & 3) * 4;
            *reinterpret_cast<float4*>(Wsh + k * W_STRIDE + n0) = Wg4[i];
        }
    }

    // X base: lane's column within this warp's 4 rows. Row r at +r*K_DIM,
    // chunk c at +c*32. Warp per (r,c): 128B coalesced LDG.
    const float* gx = Xf + (size_t)wrow0 * K_DIM + lane;

    // Register prefetch pipeline: chunks 0..D_PRE-1 (issued before the W barrier
    // so DRAM latency overlaps the W staging + syncthreads)
    float xp[D_PRE][ROWS_PER_WARP];
#pragma unroll
    for (int j = 0; j < D_PRE; ++j)
#pragma unroll
        for (int r = 0; r < ROWS_PER_WARP; ++r)
            xp[j][r] = gx[(size_t)r * K_DIM + j * 32];

    __syncthreads();   // W visible to all warps

    // acc[r*8+p] packs (anchor p: class0, class1) for local row r
    unsigned long long acc[32];
#pragma unroll
    for (int j = 0; j < 32; ++j) acc[j] = 0ULL;

    // Main: outer cc = 0,8,16 — compute chunk cc+j, refill xp[j] with cc+j+8.
#pragma unroll 1
    for (int cc = 0; cc < NCHUNKS - D_PRE; cc += D_PRE) {
#pragma unroll
        for (int j = 0; j < D_PRE; ++j) {
            const int c = cc + j;
            do_chunk(acc, Wsh, xp[j], c, lane);
#pragma unroll
            for (int r = 0; r < ROWS_PER_WARP; ++r)
                xp[j][r] = gx[(size_t)r * K_DIM + (c + D_PRE) * 32];
        }
    }
    // Tail: chunks 24..31 already in registers
#pragma unroll
    for (int j = 0; j < D_PRE; ++j)
        do_chunk(acc, Wsh, xp[j], NCHUNKS - D_PRE + j, lane);

    // Multi-value butterfly: 32 packed values over 32 lanes -> 1 per lane.
    // Lane L ends owning value j=L: local row L>>3, anchor L&7.
#pragma unroll
    for (int lvl = 0; lvl < 5; ++lvl) {
        const int m = 16 >> lvl;
        const bool up = (lane & m) != 0;
#pragma unroll
        for (int i = 0; i < 32; ++i) {
            if (i >= m) continue;
            const unsigned long long sent = up ? acc[i] : acc[m + i];
            const unsigned long long rcv = __shfl_xor_sync(0xffffffffu, sent, m);
            acc[i] = up ? add2r(acc[m + i], rcv) : add2r(acc[i], rcv);
        }
    }

    // Epilogue: one (row, anchor) per lane
    const int r_loc = lane >> 3;
    const int a = lane & 7;
    const int row = wrow0 + r_loc;

    float l0, l1;
    unpack2(acc[0], l0, l1);
    l0 += __ldg(&bias[2 * a]);
    l1 += __ldg(&bias[2 * a + 1]);

    const int lab = __ldg(&labels[row * ANCHORS + a]);
    const bool valid = (lab != -1);
    const int pred = (l1 > l0) ? 1 : 0;   // argmax, tie -> 0

    const float mx = fmaxf(l0, l1);
    const float mn = fminf(l0, l1);
    const float lse = mx + log1pf(expf(mn - mx));
    const float picked = (lab > 0) ? l1 : l0;   // clamp(-1)->0 picks l0
    const float nll = valid ? (lse - picked) : 0.0f;

    const int idx = row * ANCHORS + a;    // warp writes 128B contiguous
    out[1 + idx] = (float)pred;
    out[1 + PRED_ELEMS + idx] = (pred == 1 && valid) ? 1.0f : 0.0f;

    // Loss: warp -> block -> per-block partial
    float nll_w = nll;
    int cnt_w = valid ? 1 : 0;
#pragma unroll
    for (int s = 16; s > 0; s >>= 1) {
        nll_w += __shfl_xor_sync(0xffffffffu, nll_w, s);
        cnt_w += __shfl_xor_sync(0xffffffffu, cnt_w, s);
    }
    if (lane == 0) { s_nll[wid] = nll_w; s_cnt[wid] = cnt_w; }
    __syncthreads();

    if (tid == 0) {
        float bn = 0.f; int bc = 0;
#pragma unroll
        for (int i = 0; i < WARPS_PER_BLOCK; ++i) { bn += s_nll[i]; bc += s_cnt[i]; }
        g_part_nll[blockIdx.x] = bn;
        g_part_cnt[blockIdx.x] = bc;
        __threadfence();
        const unsigned int old = atomicAdd(&g_done, 1u);
        s_last = (old == NBLOCKS - 1) ? 1 : 0;
    }
    __syncthreads();

    // Last-arriving block performs the final loss reduction (no extra launch).
    if (s_last) {
        __shared__ double f_sum[WARPS_PER_BLOCK];
        __shared__ int    f_cnt[WARPS_PER_BLOCK];
        double sum = (double)g_part_nll[tid];   // NBLOCKS == THREADS
        int cnt = g_part_cnt[tid];
#pragma unroll
        for (int s = 16; s > 0; s >>= 1) {
            sum += __shfl_xor_sync(0xffffffffu, sum, s);
            cnt += __shfl_xor_sync(0xffffffffu, cnt, s);
        }
        if (lane == 0) { f_sum[wid] = sum; f_cnt[wid] = cnt; }
        __syncthreads();
        if (tid == 0) {
            double t = 0.0; int c = 0;
#pragma unroll
            for (int i = 0; i < WARPS_PER_BLOCK; ++i) { t += f_sum[i]; c += f_cnt[i]; }
            const double denom = c > 1 ? (double)c : 1.0;
            out[0] = (float)(t / denom);
            g_done = 0u;   // reset for next graph replay
        }
    }
}

extern "C" void kernel_launch(void* const* d_in, const int* in_sizes, int n_in,
                              void* d_out, int out_size) {
    const float* Xf = (const float*)d_in[0];   // batch_input (64,512,1024) f32
    const float* Wg = (const float*)d_in[1];   // W (1024,16) f32
    const float* b  = (const float*)d_in[2];   // b (16,) f32
    const int*   lb = (const int*)d_in[3];     // anchor_labels (64,512,8) i32
    float* out = (float*)d_out;

    cudaFuncSetAttribute(rpn_main_kernel,
                         cudaFuncAttributeMaxDynamicSharedMemorySize, SMEM_BYTES);
    rpn_main_kernel<<<NBLOCKS, THREADS, SMEM_BYTES>>>(Xf, Wg, b, lb, out);
}

// round 14
// speedup vs baseline: 1.4352x; 1.4352x over previous
#include <cuda_runtime.h>
#include <cuda_bf16.h>
#include <math.h>

// Problem constants
#define ROWS_TOTAL 32768
#define K_DIM 1024
#define ANCHORS 8
#define PRED_ELEMS (ROWS_TOTAL * ANCHORS)   // 262144

// One 512-thread CTA = 16 autonomous warps. Warp w owns rows row0+4w..+3,
// all 16 outputs. Block covers 64 rows. (R10 tile — best so far.)
#define THREADS 512
#define WARPS_PER_BLOCK 16
#define ROWS_PER_WARP 4
#define ROWS_PER_BLOCK 64
#define NBLOCKS (ROWS_TOTAL / ROWS_PER_BLOCK)   // 512
#define NCHUNKS 32                              // K chunks of 32
#define NBUF 8                                  // per-warp X ring depth (pow2)
#define LOOKAHEAD 6

// W in shared, padded stride 20 floats. LDS.128 8-lane phase banks
// 20L mod 32 = {0,20,8,28,16,4,24,12} -> all 32 banks once -> conflict-free.
#define W_STRIDE 20
#define W_FLOATS (K_DIM * W_STRIDE)             // 80KB
// Per-warp X ring: NBUF chunks x (4 rows x 32 k) = 8*128 floats = 4KB
#define XW_FLOATS (NBUF * 128)
#define SMEM_BYTES ((W_FLOATS + WARPS_PER_BLOCK * XW_FLOATS) * 4)  // 144KB

__device__ float g_part_nll[NBLOCKS];
__device__ int   g_part_cnt[NBLOCKS];
__device__ unsigned int g_done;   // zero-init; finalizer resets -> replay-safe

__device__ __forceinline__ void fma2(unsigned long long& d,
                                     unsigned long long a,
                                     unsigned long long b) {
    asm("fma.rn.f32x2 %0, %1, %2, %0;" : "+l"(d) : "l"(a), "l"(b));
}
__device__ __forceinline__ unsigned long long add2r(unsigned long long a,
                                                    unsigned long long b) {
    asm("add.rn.f32x2 %0, %0, %1;" : "+l"(a) : "l"(b));
    return a;
}
__device__ __forceinline__ unsigned long long pack_dup(float x) {
    unsigned long long r;
    asm("mov.b64 %0, {%1, %1};" : "=l"(r) : "r"(__float_as_uint(x)));
    return r;
}
__device__ __forceinline__ void unpack2(unsigned long long v, float& lo, float& hi) {
    unsigned int l, h;
    asm("mov.b64 {%0, %1}, %2;" : "=r"(l), "=r"(h) : "l"(v));
    lo = __uint_as_float(l);
    hi = __uint_as_float(h);
}
__device__ __forceinline__ void cp_async16(unsigned int sdst, const void* gsrc) {
    asm volatile("cp.async.cg.shared.global [%0], [%1], 16;"
                 :: "r"(sdst), "l"(gsrc) : "memory");
}
__device__ __forceinline__ void cp_commit() {
    asm volatile("cp.async.commit_group;" ::: "memory");
}
template <int N>
__device__ __forceinline__ void cp_wait() {
    asm volatile("cp.async.wait_group %0;" :: "n"(N) : "memory");
}

// Per-chunk register stage: 16 W floats (8 f32x2) + 4 X floats
struct Chunk {
    ulonglong2 wa, wb, wc, wd;
    float xr0, xr1, xr2, xr3;
};

__device__ __forceinline__ void load_chunk(Chunk& ch, const float* __restrict__ Wsh,
                                           const float* __restrict__ xw,
                                           int c, int lane) {
    const int k = c * 32 + lane;
    const float* wp = Wsh + k * W_STRIDE;
    ch.wa = *reinterpret_cast<const ulonglong2*>(wp);
    ch.wb = *reinterpret_cast<const ulonglong2*>(wp + 4);
    ch.wc = *reinterpret_cast<const ulonglong2*>(wp + 8);
    ch.wd = *reinterpret_cast<const ulonglong2*>(wp + 12);
    const float* xb = xw + (c & (NBUF - 1)) * 128 + lane;
    ch.xr0 = xb[0];
    ch.xr1 = xb[32];
    ch.xr2 = xb[64];
    ch.xr3 = xb[96];
}

__device__ __forceinline__ void compute_chunk(unsigned long long* __restrict__ acc,
                                              const Chunk& ch) {
    const float xs[ROWS_PER_WARP] = {ch.xr0, ch.xr1, ch.xr2, ch.xr3};
#pragma unroll
    for (int r = 0; r < ROWS_PER_WARP; ++r) {
        const unsigned long long xx = pack_dup(xs[r]);
        fma2(acc[r * 8 + 0], xx, ch.wa.x);
        fma2(acc[r * 8 + 1], xx, ch.wa.y);
        fma2(acc[r * 8 + 2], xx, ch.wb.x);
        fma2(acc[r * 8 + 3], xx, ch.wb.y);
        fma2(acc[r * 8 + 4], xx, ch.wc.x);
        fma2(acc[r * 8 + 5], xx, ch.wc.y);
        fma2(acc[r * 8 + 6], xx, ch.wd.x);
        fma2(acc[r * 8 + 7], xx, ch.wd.y);
    }
}

__global__ __launch_bounds__(THREADS, 1)
void rpn_main_kernel(const float*  __restrict__ Xf,     // [32768][1024]
                     const float*  __restrict__ Wg,     // [1024][16]
                     const float*  __restrict__ bias,   // [16]
                     const int*    __restrict__ labels, // [32768][8]
                     float* __restrict__ out)
{
    extern __shared__ __align__(16) float smem[];
    float* Wsh = smem;                        // [1024][20]
    float* Xsh = smem + W_FLOATS;             // [16 warps][NBUF][128]
    __shared__ float s_nll[WARPS_PER_BLOCK];
    __shared__ int   s_cnt[WARPS_PER_BLOCK];
    __shared__ int   s_last;

    const int tid  = threadIdx.x;
    const int wid  = tid >> 5;
    const int lane = tid & 31;
    const int row0 = blockIdx.x * ROWS_PER_BLOCK;
    const int wrow0 = row0 + wid * ROWS_PER_WARP;

    float* xw = Xsh + wid * XW_FLOATS;
    const unsigned int xw_u32 = (unsigned int)__cvta_generic_to_shared(xw);

    // Per-lane staging: lane L moves 16B: row L>>3, 16B segment L&7 of a 128B row-chunk.
    const int st_r = lane >> 3;
    const int st_s = lane & 7;
    const char* gb = (const char*)(Xf + (size_t)(wrow0 + st_r) * K_DIM) + st_s * 16;
    const unsigned int sb = xw_u32 + st_r * 128 + st_s * 16;

    // Prologue: start chunks 0..LOOKAHEAD-1 on this warp's private ring
#pragma unroll
    for (int j = 0; j < LOOKAHEAD; ++j) {
        cp_async16(sb + j * 512, gb + j * 128);
        cp_commit();
    }

    // Stage W (vectorized STS.128 into padded layout) while X flows
    {
        const float4* Wg4 = reinterpret_cast<const float4*>(Wg);
        for (int i = tid; i < K_DIM * 4; i += THREADS) {
            const int k  = i >> 2;
            const int n0 = (i & 3) * 4;
            *reinterpret_cast<float4*>(Wsh + k * W_STRIDE + n0) = Wg4[i];
        }
    }
    __syncthreads();   // W visible to all warps

    // acc[r*8+p] packs (anchor p: class0, class1) for local row r
    unsigned long long acc[32];
#pragma unroll
    for (int j = 0; j < 32; ++j) acc[j] = 0ULL;

    Chunk ch0, ch1;
    cp_wait<LOOKAHEAD - 2>();   // chunks 0 and 1 resident
    __syncwarp();
    load_chunk(ch0, Wsh, xw, 0, lane);
    load_chunk(ch1, Wsh, xw, 1, lane);

    // Main loop, unrolled by 2 (ping-pong, no struct copies).
    // Iter c: issue chunks c+6, c+7; compute c, c+1; reload ch0<-c+2, ch1<-c+3.
    // Group accounting (verified at c=0): after issuing c+7, groups younger
    // than chunk c+2 number 5 -> wait<5>; younger than c+3 -> wait<4>.
#pragma unroll 1
    for (int c = 0; c <= NCHUNKS - 2 - LOOKAHEAD; c += 2) {
        cp_async16(sb + ((c + LOOKAHEAD) & (NBUF - 1)) * 512,
                   gb + (c + LOOKAHEAD) * 128);
        cp_commit();
        cp_async16(sb + ((c + LOOKAHEAD + 1) & (NBUF - 1)) * 512,
                   gb + (c + LOOKAHEAD + 1) * 128);
        cp_commit();

        cp_wait<LOOKAHEAD - 1>();   // chunk c+2 resident
        __syncwarp();
        compute_chunk(acc, ch0);
        load_chunk(ch0, Wsh, xw, c + 2, lane);

        cp_wait<LOOKAHEAD - 2>();   // chunk c+3 resident
        __syncwarp();
        compute_chunk(acc, ch1);
        load_chunk(ch1, Wsh, xw, c + 3, lane);
    }
    // After last iter (c=24): chunks 0..25 computed, ch0=26, ch1=27,
    // all 32 chunks issued. Drain; everything resident afterwards.
    cp_wait<0>();
    __syncwarp();
    compute_chunk(acc, ch0);
    compute_chunk(acc, ch1);
#pragma unroll
    for (int c = NCHUNKS - LOOKAHEAD + 2; c < NCHUNKS; ++c) {   // 28..31
        load_chunk(ch0, Wsh, xw, c, lane);
        compute_chunk(acc, ch0);
    }

    // Multi-value butterfly: 32 packed values over 32 lanes -> 1 per lane.
    // Lane L ends owning value j=L: local row L>>3, anchor L&7.
#pragma unroll
    for (int lvl = 0; lvl < 5; ++lvl) {
        const int m = 16 >> lvl;
        const bool up = (lane & m) != 0;
#pragma unroll
        for (int i = 0; i < 32; ++i) {
            if (i >= m) continue;
            const unsigned long long sent = up ? acc[i] : acc[m + i];
            const unsigned long long rcv = __shfl_xor_sync(0xffffffffu, sent, m);
            acc[i] = up ? add2r(acc[m + i], rcv) : add2r(acc[i], rcv);
        }
    }

    // Epilogue: one (row, anchor) per lane
    const int r_loc = lane >> 3;
    const int a = lane & 7;
    const int row = wrow0 + r_loc;

    float l0, l1;
    unpack2(acc[0], l0, l1);
    l0 += __ldg(&bias[2 * a]);
    l1 += __ldg(&bias[2 * a + 1]);

    const int lab = __ldg(&labels[row * ANCHORS + a]);
    const bool valid = (lab != -1);
    const int pred = (l1 > l0) ? 1 : 0;   // argmax, tie -> 0

    const float mx = fmaxf(l0, l1);
    const float mn = fminf(l0, l1);
    const float lse = mx + log1pf(expf(mn - mx));
    const float picked = (lab > 0) ? l1 : l0;   // clamp(-1)->0 picks l0
    const float nll = valid ? (lse - picked) : 0.0f;

    const int idx = row * ANCHORS + a;    // warp writes 128B contiguous
    out[1 + idx] = (float)pred;
    out[1 + PRED_ELEMS + idx] = (pred == 1 && valid) ? 1.0f : 0.0f;

    // Loss: warp -> block -> per-block partial
    float nll_w = nll;
    int cnt_w = valid ? 1 : 0;
#pragma unroll
    for (int s = 16; s > 0; s >>= 1) {
        nll_w += __shfl_xor_sync(0xffffffffu, nll_w, s);
        cnt_w += __shfl_xor_sync(0xffffffffu, cnt_w, s);
    }
    if (lane == 0) { s_nll[wid] = nll_w; s_cnt[wid] = cnt_w; }
    __syncthreads();

    if (tid == 0) {
        float bn = 0.f; int bc = 0;
#pragma unroll
        for (int i = 0; i < WARPS_PER_BLOCK; ++i) { bn += s_nll[i]; bc += s_cnt[i]; }
        g_part_nll[blockIdx.x] = bn;
        g_part_cnt[blockIdx.x] = bc;
        __threadfence();
        const unsigned int old = atomicAdd(&g_done, 1u);
        s_last = (old == NBLOCKS - 1) ? 1 : 0;
    }
    __syncthreads();

    // Last-arriving block performs the final loss reduction (no extra launch).
    if (s_last) {
        __shared__ double f_sum[WARPS_PER_BLOCK];
        __shared__ int    f_cnt[WARPS_PER_BLOCK];
        double sum = (double)g_part_nll[tid];   // NBLOCKS == THREADS
        int cnt = g_part_cnt[tid];
#pragma unroll
        for (int s = 16; s > 0; s >>= 1) {
            sum += __shfl_xor_sync(0xffffffffu, sum, s);
            cnt += __shfl_xor_sync(0xffffffffu, cnt, s);
        }
        if (lane == 0) { f_sum[wid] = sum; f_cnt[wid] = cnt; }
        __syncthreads();
        if (tid == 0) {
            double t = 0.0; int c = 0;
#pragma unroll
            for (int i = 0; i < WARPS_PER_BLOCK; ++i) { t += f_sum[i]; c += f_cnt[i]; }
            const double denom = c > 1 ? (double)c : 1.0;
            out[0] = (float)(t / denom);
            g_done = 0u;   // reset for next graph replay
        }
    }
}

extern "C" void kernel_launch(void* const* d_in, const int* in_sizes, int n_in,
                              void* d_out, int out_size) {
    const float* Xf = (const float*)d_in[0];   // batch_input (64,512,1024) f32
    const float* Wg = (const float*)d_in[1];   // W (1024,16) f32
    const float* b  = (const float*)d_in[2];   // b (16,) f32
    const int*   lb = (const int*)d_in[3];     // anchor_labels (64,512,8) i32
    float* out = (float*)d_out;

    cudaFuncSetAttribute(rpn_main_kernel,
                         cudaFuncAttributeMaxDynamicSharedMemorySize, SMEM_BYTES);
    rpn_main_kernel<<<NBLOCKS, THREADS, SMEM_BYTES>>>(Xf, Wg, b, lb, out);
}